// round 17
// baseline (speedup 1.0000x reference)
#include <cuda_runtime.h>
#include <cuda_fp16.h>
#include <math.h>
#include <stdint.h>

#define BQ  128
#define KK_ 49
#define DD  512
#define EE  256
#define VV  10000
#define TT  20
#define G4  2048
#define NW  2176
#define PODS 8
typedef __half fp16;

// -------------------- device scratch (static) --------------------
__device__ __align__(128) fp16 g_embf[BQ*TT*EE];
__device__ __align__(128) fp16 g_glf[BQ*DD];
__device__ __align__(128) fp16 g_wihef[G4*EE];
__device__ __align__(128) fp16 g_wcatf[3072*DD];   // [Winit_h;Winit_m;W_ih_D]
__device__ __align__(128) fp16 g_wc2f[NW*DD];      // [W_hh permuted; Wg]
__device__ __align__(128) fp16 g_wvf[KK_*DD];
__device__ __align__(128) fp16 g_wpf[VV*DD];
__device__ __align__(128) fp16 g_spf[BQ*KK_*DD];
__device__ __align__(128) fp16 g_hf[BQ*DD];
__device__ __align__(128) fp16 g_sf[BQ*TT*DD];     // compacted s
__device__ __align__(128) fp16 g_hh[BQ*TT*DD];     // compacted h history
__device__ __align__(128) float g_alpha[BQ*TT*52];
__device__ __align__(128) float g_gatesx[BQ*TT*G4];
__device__ __align__(128) float g_ipart[4][BQ*3072];
__device__ __align__(128) float g_vpart[2][BQ*KK_*KK_];
__device__ int g_rmap[BQ*TT];
__device__ int g_mact;
__device__ unsigned g_f2[PODS][17][32];  // monotonic flags: j<16 h-slice, j=16 CTA16 ack

// -------------------- helpers --------------------
__device__ __forceinline__ uint32_t su(const void* p) {
    return (uint32_t)__cvta_generic_to_shared(p);
}
__device__ __forceinline__ void cpa16(uint32_t sa, const void* ga, uint32_t sz) {
    asm volatile("cp.async.cg.shared.global [%0],[%1],16,%2;\n" :: "r"(sa), "l"(ga), "r"(sz));
}
__device__ __forceinline__ void cpcommit() { asm volatile("cp.async.commit_group;\n"); }
template<int N> __device__ __forceinline__ void cpwait() {
    asm volatile("cp.async.wait_group %0;\n" :: "n"(N));
}
__device__ __forceinline__ void ldsm4(uint32_t* r, uint32_t a) {
    asm volatile("ldmatrix.sync.aligned.m8n8.x4.shared.b16 {%0,%1,%2,%3},[%4];\n"
                 : "=r"(r[0]), "=r"(r[1]), "=r"(r[2]), "=r"(r[3]) : "r"(a));
}
__device__ __forceinline__ void mmah(float* c, const uint32_t* a, uint32_t b0, uint32_t b1) {
    asm volatile(
        "mma.sync.aligned.m16n8k16.row.col.f32.f16.f16.f32 "
        "{%0,%1,%2,%3},{%4,%5,%6,%7},{%8,%9},{%0,%1,%2,%3};\n"
        : "+f"(c[0]), "+f"(c[1]), "+f"(c[2]), "+f"(c[3])
        : "r"(a[0]), "r"(a[1]), "r"(a[2]), "r"(a[3]), "r"(b0), "r"(b1));
}
__device__ __forceinline__ float fsig(float x) { return 1.f / (1.f + __expf(-x)); }
__device__ __forceinline__ float ftanh(float x) {
    float e = __expf(2.f * x);
    return 1.f - 2.f / (e + 1.f);
}
__device__ __forceinline__ void strel(unsigned* p, unsigned v) {
    asm volatile("st.release.gpu.u32 [%0],%1;" :: "l"(p), "r"(v) : "memory");
}
__device__ __forceinline__ unsigned ldacq(const unsigned* p) {
    unsigned v;
    asm volatile("ld.acquire.gpu.u32 %0,[%1];" : "=r"(v) : "l"(p) : "memory");
    return v;
}
__device__ __forceinline__ void waitflag(const unsigned* p, unsigned tgt) {
    unsigned v = ldacq(p);
    while ((int)(v - tgt) < 0) v = ldacq(p);
}

// -------------------- shared fp16 GEMM body (128x128 tile, 2-stage) --------------------
#define SST   40
#define FMATB (128 * SST)

__device__ __forceinline__ void gemm_body(
    const fp16* __restrict__ A, int lda,
    const fp16* __restrict__ B, int ldb,
    float* __restrict__ C, int ldc,
    int Meff, int N, int K, int bm, int bn,
    const float* __restrict__ bias, int useRmap, char* smraw)
{
    fp16* sm = (fp16*)smraw;
    const int tid = threadIdx.x;
    const int w = tid >> 5, lane = tid & 31;
    const int wm = w >> 2, wn = w & 3;
    const int g = lane >> 2, tg = lane & 3;
    const int lrow = lane & 15, lcol = (lane >> 4) * 8;
    const int ldrow = tid >> 1, ldch = (tid & 1) * 2;

    const fp16* aSrc = A + (size_t)(bm + ldrow) * lda + ldch * 8;
    int gn_l = bn + ldrow;
    uint32_t szb = (gn_l < N) ? 16u : 0u;
    if (gn_l >= N) gn_l = 0;
    const fp16* bSrc = B + (size_t)gn_l * ldb + ldch * 8;
    const uint32_t da = su(sm + ldrow * SST + ldch * 8);
    const uint32_t db = da + FMATB * 2;

    float acc[4][4][4];
#pragma unroll
    for (int i = 0; i < 4; i++)
#pragma unroll
        for (int j = 0; j < 4; j++)
#pragma unroll
            for (int q = 0; q < 4; q++) acc[i][j][q] = 0.f;

    auto issue = [&](int stg, int k0) {
        uint32_t so = (uint32_t)(stg * 2 * FMATB) * 2;
        cpa16(da + so,      aSrc + k0,     16);
        cpa16(da + so + 16, aSrc + k0 + 8, 16);
        cpa16(db + so,      bSrc + k0,     szb);
        cpa16(db + so + 16, bSrc + k0 + 8, szb);
    };

    const int niter = K / 32;
    issue(0, 0);
    cpcommit();
    int st = 0;
    for (int it = 0; it < niter; ++it) {
        if (it + 1 < niter) {
            issue(st ^ 1, (it + 1) * 32);
            cpcommit();
            cpwait<1>();
        } else {
            cpwait<0>();
        }
        __syncthreads();
        const fp16* base = sm + st * 2 * FMATB;
#pragma unroll
        for (int ks = 0; ks < 32; ks += 16) {
            uint32_t ah[4][4], bh[2][4];
#pragma unroll
            for (int mi = 0; mi < 4; mi++)
                ldsm4(ah[mi], su(base + (wm * 64 + mi * 16 + lrow) * SST + ks + lcol));
#pragma unroll
            for (int p = 0; p < 2; p++)
                ldsm4(bh[p], su(base + FMATB + (wn * 32 + p * 16 + lrow) * SST + ks + lcol));
#pragma unroll
            for (int mi = 0; mi < 4; mi++)
#pragma unroll
                for (int ni = 0; ni < 4; ni++) {
                    const int p = ni >> 1, q = ni & 1;
                    mmah(acc[mi][ni], ah[mi], bh[p][q], bh[p][q + 2]);
                }
        }
        __syncthreads();
        st ^= 1;
    }

#pragma unroll
    for (int mi = 0; mi < 4; mi++)
#pragma unroll
        for (int ni = 0; ni < 4; ni++) {
            int gn0 = bn + wn * 32 + ni * 8 + tg * 2;
#pragma unroll
            for (int half = 0; half < 2; half++) {
                int gm = bm + wm * 64 + mi * 16 + g + half * 8;
                if (gm >= Meff) continue;
                int orow = useRmap ? g_rmap[gm] : gm;
#pragma unroll
                for (int q = 0; q < 2; q++) {
                    int gn = gn0 + q;
                    if (gn >= N) continue;
                    float v = acc[mi][ni][half * 2 + q];
                    if (bias) v += bias[gn];
                    C[(size_t)orow * ldc + gn] = v;
                }
            }
        }
}

// -------------------- fp32 -> fp16 converter (+perm) (+ build_map) --------------------
struct Seg { const float4* src; uint2* dst; int srcld4; int lc4; int perm; long long start; };
struct SegArr { Seg s[10]; long long total; };

__global__ void conv_all(SegArr sa, const int* __restrict__ lengths) {
    if (blockIdx.x == gridDim.x - 1) {
        __shared__ int cnt[20], off[21];
        int tid = threadIdx.x;
        if (tid < 20) {
            int c = 0;
            for (int b = 0; b < BQ; b++) c += (lengths[b] > tid);
            cnt[tid] = c;
        }
        __syncthreads();
        if (tid == 0) {
            off[0] = 0;
            for (int t = 0; t < 20; t++) off[t + 1] = off[t] + cnt[t];
            g_mact = off[20];
        }
        __syncthreads();
        for (int t = 0; t < 20; t++)
            for (int b = tid; b < cnt[t]; b += 256)
                g_rmap[off[t] + b] = b * TT + t;
        return;
    }
    long long i = (long long)blockIdx.x * blockDim.x + threadIdx.x;
    if (i >= sa.total) return;
    int k = 0;
#pragma unroll
    for (int j = 1; j < 10; j++) if (i >= sa.s[j].start) k = j;
    Seg sg = sa.s[k];
    long long idx = i - sg.start;
    int row = (int)(idx >> sg.lc4);
    int c   = (int)(idx & ((1 << sg.lc4) - 1));
    float4 v = sg.src[(long long)row * sg.srcld4 + c];
    if (sg.perm) {
        // W_hh row gate*512+dd  ->  dest row (dd/32)*128 + gate*32 + dd%32
        int gate = row >> 9, dd = row & 511;
        row = (dd >> 5) * 128 + (gate << 5) + (dd & 31);
    }
    __half2 a = __floats2half2_rn(v.x, v.y);
    __half2 b = __floats2half2_rn(v.z, v.w);
    uint2 o;
    o.x = *reinterpret_cast<uint32_t*>(&a);
    o.y = *reinterpret_cast<uint32_t*>(&b);
    sg.dst[(long long)row * (1 << sg.lc4) + c] = o;
}

// -------------------- embedding gather (compact, fp16) --------------------
__global__ void gather_emb(const int* __restrict__ cap, const float* __restrict__ emb) {
    int i = blockIdx.x * blockDim.x + threadIdx.x;
    if (i >= BQ * TT * (EE / 4)) return;
    int r = i >> 6, e4 = i & 63;
    if (r >= g_mact) return;
    int tok = cap[g_rmap[r]];
    float4 v = reinterpret_cast<const float4*>(emb)[(size_t)tok * 64 + e4];
    __half2 a = __floats2half2_rn(v.x, v.y);
    __half2 b = __floats2half2_rn(v.z, v.w);
    uint2 o;
    o.x = *reinterpret_cast<uint32_t*>(&a);
    o.y = *reinterpret_cast<uint32_t*>(&b);
    reinterpret_cast<uint2*>(g_embf)[(size_t)r * 64 + e4] = o;
}

// -------------------- fused pre-pass: vproj + gates_x + init + zfill --------------------
__global__ void __launch_bounds__(256, 2) multi_pre(
    const int* __restrict__ lengths, float* __restrict__ out)
{
    extern __shared__ __align__(16) char smraw[];
    const int bx = blockIdx.x;
    if (bx < 98) {
        int y = bx % 49, kz = bx / 49;
        gemm_body(g_spf + kz * 256, DD, g_wvf + kz * 256, DD,
                  g_vpart[kz], KK_, BQ * KK_, KK_, 256, y * 128, 0,
                  nullptr, 0, smraw);
    } else if (bx < 418) {
        int i = bx - 98;
        int x = i & 15, y = i >> 4;
        int mact = g_mact;
        if (y * 128 >= mact) return;
        gemm_body(g_embf, EE, g_wihef, EE, g_gatesx, G4,
                  mact, G4, EE, y * 128, x * 128, nullptr, 0, smraw);
    } else if (bx < 514) {
        int i = bx - 418;
        int x = i % 24, kz = i / 24;
        gemm_body(g_glf + kz * 128, DD, g_wcatf + kz * 128, DD,
                  g_ipart[kz], 3072, BQ, 3072, 128, 0, x * 128,
                  nullptr, 0, smraw);
    } else {
        int i = bx - 514;
        float4 z = make_float4(0.f, 0.f, 0.f, 0.f);
#pragma unroll
        for (int k = 0; k < 4; k++) {
            int row = i * 4 + k;
            int b = row / TT, t = row % TT;
            if (lengths[b] > t) continue;
            float4* o = reinterpret_cast<float4*>(out + (size_t)row * VV);
            for (int q = threadIdx.x; q < VV / 4; q += 256) o[q] = z;
        }
    }
}

// -------------------- context kernel: s = alpha @ spatial + h_hist --------------------
__global__ void __launch_bounds__(256, 4) ctx_kernel()
{
    int r = blockIdx.x;
    if (r >= g_mact) return;
    __shared__ float sal[52];
    int tid = threadIdx.x;
    if (tid < KK_) sal[tid] = g_alpha[(size_t)r * 52 + tid];
    __syncthreads();
    int b = g_rmap[r] / TT;
    const __half2* sp2 = (const __half2*)(g_spf + (size_t)b * KK_ * DD);
    float ccx = 0.f, ccy = 0.f;
#pragma unroll
    for (int k = 0; k < KK_; k++) {
        float al = sal[k];
        float2 f = __half22float2(sp2[k * 256 + tid]);
        ccx = fmaf(al, f.x, ccx);
        ccy = fmaf(al, f.y, ccy);
    }
    float2 h = __half22float2(((const __half2*)g_hh)[(size_t)r * 256 + tid]);
    ((__half2*)g_sf)[(size_t)r * 256 + tid] = __floats2half2_rn(ccx + h.x, ccy + h.y);
}

// -------------------- vocab GEMM --------------------
__global__ void __launch_bounds__(256, 2) gemm_vocab(
    float* __restrict__ out, const float* __restrict__ bias)
{
    int mact = g_mact;
    if ((int)blockIdx.y * 128 >= mact) return;
    extern __shared__ __align__(16) char smraw[];
    gemm_body(g_sf, DD, g_wpf, DD, out, VV, mact, VV, DD,
              blockIdx.y * 128, blockIdx.x * 128, bias, 1, smraw);
}

// -------------------- recurrence: gate-dim sliced pods, one flag hop/step --------------
#define RST2 520
#define SGP  132
#define TAILOFF 176128
#define RSM2 176640

__global__ __launch_bounds__(256, 1) void recur_kernel(
    const float* __restrict__ b_hh,
    const int*   __restrict__ lengths,
    const float* __restrict__ bg,
    const float* __restrict__ wh,
    const float* __restrict__ bh_att,
    const float* __restrict__ b_init_h,
    const float* __restrict__ b_init_m,
    const float* __restrict__ b_ih,
    const float* __restrict__ bv)
{
    extern __shared__ __align__(16) char dsm[];
    const int c = blockIdx.x;
    const int p = c / 17, j = c % 17;
    const int pb0 = p * 16;
    const int tid = threadIdx.x;
    const int w = tid >> 5, lane = tid & 31;
    const int g = lane >> 2, tg = lane & 3;
    const int lrow = lane & 15, lcol = (lane >> 4) * 8;

    // tail smem (common)
    int* rs_cnt = (int*)(dsm + TAILOFF);     // [21]
    int* rs_off = rs_cnt + 21;               // [22]
    int* slen   = rs_off + 22;               // [16]
    unsigned* sbase = (unsigned*)(slen + 16);

    if (tid == 0) sbase[0] = ldacq(&g_f2[p][j][0]);
    if (tid < 21) {
        int cc = 0;
        for (int bb = 0; bb < BQ; bb++) cc += (lengths[bb] > tid);
        rs_cnt[tid] = cc;
    }
    if (tid >= 32 && tid < 48) slen[tid - 32] = lengths[pb0 + tid - 32];
    __syncthreads();
    if (tid == 0) {
        rs_off[0] = 0;
        for (int u = 0; u < 21; u++) rs_off[u + 1] = rs_off[u] + rs_cnt[u];
    }
    __syncthreads();
    const unsigned B = sbase[0];

    int pod_len = 0;
#pragma unroll
    for (int q = 0; q < 16; q++) pod_len = slen[q] > pod_len ? slen[q] : pod_len;

    if (j < 16) {
        // =============== PRODUCER CTA: gates+LSTM for dims [32j,32j+32) ===============
        fp16* sB = (fp16*)dsm;                       // [128][RST2]
        fp16* sA = sB + 128 * RST2;                  // [16][RST2]
        float* sG  = (float*)(sA + 16 * RST2);       // [16][SGP]
        float* sGX = sG + 16 * SGP;                  // [16][128]

        // prologue: W slice (permuted rows), sGX = gxg+b_ih+b_hh, h0, m0
#pragma unroll
        for (int k = 0; k < 32; k++) {
            int cid = tid + k * 256;
            int row = cid >> 6, ch = cid & 63;
            *(float4*)(sB + row * RST2 + ch * 8) =
                *(const float4*)(g_wc2f + (size_t)(j * 128 + row) * DD + ch * 8);
        }
#pragma unroll
        for (int k = 0; k < 8; k++) {
            int idx = tid + k * 256;            // 0..2047
            int b = idx >> 7, cc = idx & 127;
            int gate = cc >> 5, dl = cc & 31;
            int col = gate * 512 + j * 32 + dl;
            float v = g_ipart[0][(pb0 + b) * 3072 + 1024 + col]
                    + g_ipart[1][(pb0 + b) * 3072 + 1024 + col]
                    + g_ipart[2][(pb0 + b) * 3072 + 1024 + col]
                    + g_ipart[3][(pb0 + b) * 3072 + 1024 + col];
            sGX[b * 128 + cc] = v + b_ih[col] + b_hh[col];
        }
#pragma unroll
        for (int k = 0; k < 2; k++) {
            int idx = tid + k * 256;            // 0..511
            int b = idx >> 5, dl = idx & 31;
            int col = j * 32 + dl;
            float v = g_ipart[0][(pb0 + b) * 3072 + col]
                    + g_ipart[1][(pb0 + b) * 3072 + col]
                    + g_ipart[2][(pb0 + b) * 3072 + col]
                    + g_ipart[3][(pb0 + b) * 3072 + col] + b_init_h[col];
            g_hf[(pb0 + b) * DD + col] = __float2half(v);
        }
        // m0 for this thread's 2 (b,d) pairs
        const int mb = tid >> 4, mdl = (tid & 15) * 2;
        float m0a, m0b;
        {
            int col = 512 + j * 32 + mdl;
            m0a = g_ipart[0][(pb0 + mb) * 3072 + col] + g_ipart[1][(pb0 + mb) * 3072 + col]
                + g_ipart[2][(pb0 + mb) * 3072 + col] + g_ipart[3][(pb0 + mb) * 3072 + col]
                + b_init_m[col - 512];
            m0b = g_ipart[0][(pb0 + mb) * 3072 + col + 1] + g_ipart[1][(pb0 + mb) * 3072 + col + 1]
                + g_ipart[2][(pb0 + mb) * 3072 + col + 1] + g_ipart[3][(pb0 + mb) * 3072 + col + 1]
                + b_init_m[col - 511];
        }
        __syncthreads();
        if (tid == 0) strel(&g_f2[p][j][0], B + 1);   // h0 slice ready

        float mr0 = m0a, mr1 = m0b;
        const int mlen = slen[mb];
        for (int t = 0; t < pod_len; t++) {
            // prefetch gatesx for this thread's pairs (flag-independent)
            const bool act = (mlen > t);
            int grow = act ? (rs_off[t] + pb0 + mb) : 0;
            float2 gxv[4];
#pragma unroll
            for (int gg = 0; gg < 4; gg++)
                gxv[gg] = *(const float2*)(g_gatesx + (size_t)grow * G4 + gg * 512 + j * 32 + mdl);

            // wait h(t) slices from all producers
            if (tid < 16) waitflag(&g_f2[p][tid][0], B + 1 + t);
            __syncthreads();
#pragma unroll
            for (int k = 0; k < 4; k++) {
                int cid = tid + k * 256;
                int row = cid >> 6, ch = cid & 63;
                *(float4*)(sA + row * RST2 + ch * 8) =
                    *(const float4*)(g_hf + (size_t)(pb0 + row) * DD + ch * 8);
            }
            __syncthreads();

            // GEMM: [16 x 128] = h_pod @ Wslice^T
            float a0[2][4], a1[2][4];
#pragma unroll
            for (int q = 0; q < 2; q++)
#pragma unroll
                for (int i = 0; i < 4; i++) { a0[q][i] = 0.f; a1[q][i] = 0.f; }
#pragma unroll
            for (int ks = 0; ks < 256; ks += 16) {
                uint32_t x4[4], y4[4];
                ldsm4(x4, su(sA + lrow * RST2 + ks + lcol));
                ldsm4(y4, su(sB + (w * 16 + lrow) * RST2 + ks + lcol));
                mmah(a0[0], x4, y4[0], y4[2]);
                mmah(a0[1], x4, y4[1], y4[3]);
                ldsm4(x4, su(sA + lrow * RST2 + ks + 256 + lcol));
                ldsm4(y4, su(sB + (w * 16 + lrow) * RST2 + ks + 256 + lcol));
                mmah(a1[0], x4, y4[0], y4[2]);
                mmah(a1[1], x4, y4[1], y4[3]);
            }
#pragma unroll
            for (int q = 0; q < 2; q++) {
                int col = w * 16 + q * 8 + tg * 2;
                sG[g * SGP + col]       = a0[q][0] + a1[q][0];
                sG[g * SGP + col + 1]   = a0[q][1] + a1[q][1];
                sG[(g + 8) * SGP + col]     = a0[q][2] + a1[q][2];
                sG[(g + 8) * SGP + col + 1] = a0[q][3] + a1[q][3];
            }
            __syncthreads();

            // backpressure: CTA16 must have copied h(t) before we overwrite it
            if (tid == 0) waitflag(&g_f2[p][16][0], B + 1 + t);
            __syncthreads();

            // LSTM for this thread's 2 dims of batch mb
            if (act) {
                float pi0 = gxv[0].x + sGX[mb * 128 + mdl]      + sG[mb * SGP + mdl];
                float pi1 = gxv[0].y + sGX[mb * 128 + mdl + 1]  + sG[mb * SGP + mdl + 1];
                float pf0 = gxv[1].x + sGX[mb * 128 + 32 + mdl]     + sG[mb * SGP + 32 + mdl];
                float pf1 = gxv[1].y + sGX[mb * 128 + 32 + mdl + 1] + sG[mb * SGP + 32 + mdl + 1];
                float pg0 = gxv[2].x + sGX[mb * 128 + 64 + mdl]     + sG[mb * SGP + 64 + mdl];
                float pg1 = gxv[2].y + sGX[mb * 128 + 64 + mdl + 1] + sG[mb * SGP + 64 + mdl + 1];
                float po0 = gxv[3].x + sGX[mb * 128 + 96 + mdl]     + sG[mb * SGP + 96 + mdl];
                float po1 = gxv[3].y + sGX[mb * 128 + 96 + mdl + 1] + sG[mb * SGP + 96 + mdl + 1];
                mr0 = fsig(pf0) * mr0 + fsig(pi0) * ftanh(pg0);
                mr1 = fsig(pf1) * mr1 + fsig(pi1) * ftanh(pg1);
                float h0 = fsig(po0) * ftanh(mr0);
                float h1 = fsig(po1) * ftanh(mr1);
                __half2 hh2 = __floats2half2_rn(h0, h1);
                *(__half2*)(g_hf + (size_t)(pb0 + mb) * DD + j * 32 + mdl) = hh2;
                *(__half2*)(g_hh + (size_t)(rs_off[t] + pb0 + mb) * DD + j * 32 + mdl) = hh2;
            }
            __syncthreads();
            if (tid == 0) strel(&g_f2[p][j][0], B + 2 + t);
        }
    } else {
        // =============== CTA16: attention (gh -> z -> softmax -> alpha) ===============
        fp16* sB = (fp16*)dsm;                       // [64][RST2]  Wg rows
        fp16* sA = sB + 64 * RST2;                   // [16][RST2]
        fp16* sVP = sA + 16 * RST2;                  // [16*49][52]
        float* sGH = (float*)(sVP + 16 * 49 * 52);   // [16][52]
        float* sZ  = sGH + 16 * 52;                  // [16][52]
        float* sWH = sZ + 16 * 52;                   // [52]
        float* sBG = sWH + 52;                       // [52]
        const float bh0 = bh_att[0];

        // prologue: Wg rows (64, only 49 valid), wh/bg, vproj fp16
#pragma unroll
        for (int k = 0; k < 16; k++) {
            int cid = tid + k * 256;
            int row = cid >> 6, ch = cid & 63;
            *(float4*)(sB + row * RST2 + ch * 8) =
                *(const float4*)(g_wc2f + (size_t)(2048 + row) * DD + ch * 8);
        }
        if (tid < KK_) { sWH[tid] = wh[tid]; sBG[tid] = bg[tid]; }
        for (int i = tid; i < 16 * KK_ * KK_; i += 256) {
            int bk = i / KK_, q = i - bk * KK_;
            int b = bk / KK_, kk = bk - b * KK_;
            float v = g_vpart[0][(size_t)((pb0 + b) * KK_ + kk) * KK_ + q]
                    + g_vpart[1][(size_t)((pb0 + b) * KK_ + kk) * KK_ + q] + bv[q];
            sVP[(b * KK_ + kk) * 52 + q] = __float2half(v);
        }
        __syncthreads();
        if (tid == 0) strel(&g_f2[p][16][0], B + 1);

        for (int s = 0; s < pod_len; s++) {
            // wait carry(s+1) from all producers
            if (tid < 16) waitflag(&g_f2[p][tid][0], B + 2 + s);
            __syncthreads();
#pragma unroll
            for (int k = 0; k < 4; k++) {
                int cid = tid + k * 256;
                int row = cid >> 6, ch = cid & 63;
                *(float4*)(sA + row * RST2 + ch * 8) =
                    *(const float4*)(g_hf + (size_t)(pb0 + row) * DD + ch * 8);
            }
            __syncthreads();
            if (tid == 0) strel(&g_f2[p][16][0], B + 2 + s);   // copied: safe to overwrite

            // gh GEMM: [16 x 64] (warps 0..3)
            if (w < 4) {
                float a0[2][4], a1[2][4];
#pragma unroll
                for (int q = 0; q < 2; q++)
#pragma unroll
                    for (int i = 0; i < 4; i++) { a0[q][i] = 0.f; a1[q][i] = 0.f; }
#pragma unroll
                for (int ks = 0; ks < 256; ks += 16) {
                    uint32_t x4[4], y4[4];
                    ldsm4(x4, su(sA + lrow * RST2 + ks + lcol));
                    ldsm4(y4, su(sB + (w * 16 + lrow) * RST2 + ks + lcol));
                    mmah(a0[0], x4, y4[0], y4[2]);
                    mmah(a0[1], x4, y4[1], y4[3]);
                    ldsm4(x4, su(sA + lrow * RST2 + ks + 256 + lcol));
                    ldsm4(y4, su(sB + (w * 16 + lrow) * RST2 + ks + 256 + lcol));
                    mmah(a1[0], x4, y4[0], y4[2]);
                    mmah(a1[1], x4, y4[1], y4[3]);
                }
#pragma unroll
                for (int q = 0; q < 2; q++) {
                    int col = w * 16 + q * 8 + tg * 2;
#pragma unroll
                    for (int e = 0; e < 2; e++) {
                        if (col + e < KK_) {
                            sGH[g * 52 + col + e]       = a0[q][e]     + a1[q][e]     + sBG[col + e];
                            sGH[(g + 8) * 52 + col + e] = a0[q][2 + e] + a1[q][2 + e] + sBG[col + e];
                        }
                    }
                }
            }
            __syncthreads();

            // z[b][k] = sum_q tanh(vp + gh) * wh + bh
            for (int idx = tid; idx < 16 * KK_; idx += 256) {
                int b = idx / KK_, kk = idx - b * KK_;
                const fp16* vp = sVP + (b * KK_ + kk) * 52;
                const float* gh = sGH + b * 52;
                float acc = 0.f;
#pragma unroll 7
                for (int q = 0; q < KK_; q++)
                    acc += ftanh(__half2float(vp[q]) + gh[q]) * sWH[q];
                sZ[b * 52 + kk] = acc + bh0;
            }
            __syncthreads();

            // softmax + alpha store (warp w handles batches 2w, 2w+1)
#pragma unroll
            for (int rr = 0; rr < 2; rr++) {
                int b = w * 2 + rr;
                float mx = -3.0e38f;
                for (int k = lane; k < KK_; k += 32) mx = fmaxf(mx, sZ[b * 52 + k]);
#pragma unroll
                for (int o = 16; o; o >>= 1) mx = fmaxf(mx, __shfl_xor_sync(0xffffffffu, mx, o));
                float sm = 0.f;
                for (int k = lane; k < KK_; k += 32) {
                    float e = __expf(sZ[b * 52 + k] - mx);
                    sZ[b * 52 + k] = e;
                    sm += e;
                }
#pragma unroll
                for (int o = 16; o; o >>= 1) sm += __shfl_xor_sync(0xffffffffu, sm, o);
                float inv = 1.f / sm;
                if (slen[b] > s) {
                    float* ao = g_alpha + (size_t)(rs_off[s] + pb0 + b) * 52;
                    for (int k = lane; k < KK_; k += 32) ao[k] = sZ[b * 52 + k] * inv;
                }
            }
            __syncthreads();
        }
    }
}

// -------------------- launch --------------------
extern "C" void kernel_launch(void* const* d_in, const int* in_sizes, int n_in,
                              void* d_out, int out_size)
{
    const float* spatial      = (const float*)d_in[0];
    const float* global_feats = (const float*)d_in[1];
    const int*   captions     = (const int*)d_in[2];
    const int*   lengths      = (const int*)d_in[3];
    const float* emb          = (const float*)d_in[4];
    const float* W_init_h     = (const float*)d_in[5];
    const float* b_init_h     = (const float*)d_in[6];
    const float* W_init_m     = (const float*)d_in[7];
    const float* b_init_m     = (const float*)d_in[8];
    const float* W_ih         = (const float*)d_in[9];
    const float* b_ih         = (const float*)d_in[10];
    const float* W_hh         = (const float*)d_in[11];
    const float* b_hh         = (const float*)d_in[12];
    const float* Wv           = (const float*)d_in[13];
    const float* bv           = (const float*)d_in[14];
    const float* Wg           = (const float*)d_in[15];
    const float* bg           = (const float*)d_in[16];
    const float* wh           = (const float*)d_in[17];
    const float* bh_att       = (const float*)d_in[18];
    const float* Wp           = (const float*)d_in[19];
    const float* bp           = (const float*)d_in[20];
    float* out = (float*)d_out;

#define GETP(var, sym) void* var; cudaGetSymbolAddress(&var, sym)
    GETP(p_glf, g_glf);      GETP(p_wihef, g_wihef);
    GETP(p_wcatf, g_wcatf);  GETP(p_wc2f, g_wc2f);
    GETP(p_wvf, g_wvf);      GETP(p_wpf, g_wpf);
    GETP(p_spf, g_spf);
#undef GETP

    const int FSM = 2 * 2 * FMATB * 2;                       // 40960 B
    cudaFuncSetAttribute(multi_pre, cudaFuncAttributeMaxDynamicSharedMemorySize, FSM);
    cudaFuncSetAttribute(gemm_vocab, cudaFuncAttributeMaxDynamicSharedMemorySize, FSM);
    cudaFuncSetAttribute(recur_kernel, cudaFuncAttributeMaxDynamicSharedMemorySize, RSM2);

    // ---- 1. convert fp32 -> fp16 (+ permute W_hh, build active-row map) ----
    SegArr sa;
    long long pos = 0;
    auto seg = [&](int i, const float* src, void* dst, int srcld, int cols, int rows, int perm) {
        sa.s[i].src = (const float4*)src;
        sa.s[i].dst = (uint2*)dst;
        sa.s[i].srcld4 = srcld / 4;
        sa.s[i].lc4 = (cols / 4 == 64) ? 6 : 7;
        sa.s[i].perm = perm;
        sa.s[i].start = pos;
        pos += (long long)rows * (cols / 4);
    };
    seg(0, global_feats, p_glf, DD, DD, BQ, 0);
    seg(1, W_init_h, p_wcatf, DD, DD, DD, 0);
    seg(2, W_init_m, (fp16*)p_wcatf + 512 * DD, DD, DD, DD, 0);
    seg(3, W_ih, p_wihef, EE + DD, EE, G4, 0);
    seg(4, W_ih + EE, (fp16*)p_wcatf + 1024 * DD, EE + DD, DD, G4, 0);
    seg(5, W_hh, p_wc2f, DD, DD, G4, 1);
    seg(6, Wg, (fp16*)p_wc2f + 2048 * DD, DD, DD, KK_, 0);
    seg(7, Wv, p_wvf, DD, DD, KK_, 0);
    seg(8, Wp, p_wpf, DD, DD, VV, 0);
    seg(9, spatial, p_spf, DD, DD, BQ * KK_, 0);
    sa.total = pos;
    conv_all<<<(unsigned)((pos + 255) / 256) + 1, 256>>>(sa, lengths);

    // ---- 2. gather caption embeddings (compact, fp16) ----
    gather_emb<<<(BQ * TT * (EE / 4) + 255) / 256, 256>>>(captions, emb);

    // ---- 3. fused pre-pass: vproj + gates_x + init + zfill ----
    multi_pre<<<1154, 256, FSM>>>(lengths, out);

    // ---- 4. recurrence (gate-dim sliced, 1 flag hop/step) ----
    recur_kernel<<<136, 256, RSM2>>>(b_hh, lengths, bg, wh, bh_att,
                                     b_init_h, b_init_m, b_ih, bv);

    // ---- 5. context: s = alpha @ spatial + h_hist ----
    ctx_kernel<<<BQ * TT, 256>>>();

    // ---- 6. logits = s_compact @ Wp^T + bp, scattered via rmap ----
    gemm_vocab<<<dim3(79, 20), 256, FSM>>>(out, bp);
}